// round 13
// baseline (speedup 1.0000x reference)
#include <cuda_runtime.h>

// AMLGCN: 2x GCNConv + Linear head.
//   conv(x) = (segment_sum_dst(w_e * x[src]))@W + b   (linearity reorder)
// Pipeline (6 launches):
//   k_hist       degree histogram (g_deg zero-at-entry invariant)
//   k_scan1      shfl-based per-block exclusive scan -> partial rowptr + block sums
//   k_scan23     per-block carry + finalize rowptr + re-zero g_deg
//   k_scatter    CSR placement via atomicAdd on g_rowptr itself
//                (post-scatter: g_rowptr[d] == rowptr[d+1]; agg uses [d-1], [d])
//   k_fused      AG = agg(x) rows rowb..+63 -> smem (MLP=4); h1 = relu(AG@W1+b1) -> smem;
//                p2 = h1@W2 -> global   (TF32 mma 3-term split)
//   k_agg64_out  out = relu(agg(p2)+b2)@Wl+bl   (gather MLP=2 + fused head)
// MMA hot path is MACRO-ONLY with individually named scalar registers ->
// zero local memory. No inter-block spin anywhere. Static smem only.

#define NN 50000
#define EE 800000

// ---------------- scratch (device globals; no allocations) ----------------
__device__ int   g_deg[NN];        // zero-initialized at load; invariant: zero at entry
__device__ int   g_rowptr[NN];     // after scan23: exclusive prefix; after scatter: rowptr[d+1]
__device__ int   g_bsum[64];
__device__ int2  g_edge[EE];       // .x = src, .y = bitcast(weight)
__device__ float g_p2[(size_t)NN * 64];

// ---------------- CSR build ----------------
__global__ void k_hist(const int* __restrict__ ei) {
    int e = blockIdx.x * blockDim.x + threadIdx.x;
    if (e < EE) atomicAdd(&g_deg[ei[EE + e]], 1);
}

// shfl-based block scan (1024 threads): warp inclusive scan -> warp-sum scan -> offset
__global__ void k_scan1() {
    __shared__ int wsum[32];
    const int t    = threadIdx.x;
    const int lane = t & 31;
    const int w    = t >> 5;
    const int i    = blockIdx.x * 1024 + t;
    int v = (i < NN) ? g_deg[i] : 0;
    int s = v;
    #pragma unroll
    for (int off = 1; off < 32; off <<= 1) {
        int n = __shfl_up_sync(0xffffffffu, s, off);
        if (lane >= off) s += n;
    }
    if (lane == 31) wsum[w] = s;
    __syncthreads();
    if (w == 0) {
        int ws = wsum[lane];
        #pragma unroll
        for (int off = 1; off < 32; off <<= 1) {
            int n = __shfl_up_sync(0xffffffffu, ws, off);
            if (lane >= off) ws += n;
        }
        wsum[lane] = ws;
    }
    __syncthreads();
    int add = w ? wsum[w - 1] : 0;
    s += add;
    if (i < NN) g_rowptr[i] = s - v;          // exclusive within block (partial)
    if (t == 1023) g_bsum[blockIdx.x] = s;    // block total
}

// Each block independently computes its carry (2-warp reduce of bsum[0..b)),
// finalizes rowptr, and zeros g_deg (restores invariant).
__global__ void k_scan23() {
    __shared__ int wred[2];
    __shared__ int carry_s;
    const int t = threadIdx.x;
    const int b = blockIdx.x;
    const int i = b * 1024 + t;
    if (t < 64) {
        int c = (t < b) ? g_bsum[t] : 0;
        #pragma unroll
        for (int off = 16; off; off >>= 1) c += __shfl_down_sync(0xffffffffu, c, off);
        if ((t & 31) == 0) wred[t >> 5] = c;
    }
    __syncthreads();
    if (t == 0) carry_s = wred[0] + wred[1];
    __syncthreads();
    if (i < NN) {
        g_rowptr[i] += carry_s;
        g_deg[i] = 0;
    }
}

// scatter via atomicAdd on rowptr itself: afterwards g_rowptr[d] = rowptr[d+1]
__global__ void k_scatter(const int* __restrict__ ei, const float* __restrict__ w) {
    int e = blockIdx.x * blockDim.x + threadIdx.x;
    if (e < EE) {
        int d = ei[EE + e];
        int p = atomicAdd(&g_rowptr[d], 1);
        g_edge[p] = make_int2(ei[e], __float_as_int(w[e]));
    }
}

// agg over 64 features (MLP=2) + fused: relu(.+b2) @ Wl + bl  ->  out[N,2]
__global__ void k_agg64_out(const float* __restrict__ b2,
                            const float* __restrict__ Wl,
                            const float* __restrict__ bl,
                            float* __restrict__ out) {
    int gw   = (blockIdx.x * blockDim.x + threadIdx.x) >> 5;
    int lane = threadIdx.x & 31;
    if (gw >= NN) return;
    int beg = gw ? g_rowptr[gw - 1] : 0;
    int end = g_rowptr[gw];
    float2 acc = make_float2(0.f, 0.f);
    int e = beg;
    for (; e + 2 <= end; e += 2) {
        int2  e0 = g_edge[e], e1 = g_edge[e + 1];
        float w0 = __int_as_float(e0.y), w1 = __int_as_float(e1.y);
        float2 v0 = ((const float2*)(g_p2 + (size_t)e0.x * 64))[lane];
        float2 v1 = ((const float2*)(g_p2 + (size_t)e1.x * 64))[lane];
        acc.x = fmaf(w0, v0.x, acc.x); acc.y = fmaf(w0, v0.y, acc.y);
        acc.x = fmaf(w1, v1.x, acc.x); acc.y = fmaf(w1, v1.y, acc.y);
    }
    if (e < end) {
        int2  e0 = g_edge[e];
        float w0 = __int_as_float(e0.y);
        float2 v0 = ((const float2*)(g_p2 + (size_t)e0.x * 64))[lane];
        acc.x = fmaf(w0, v0.x, acc.x); acc.y = fmaf(w0, v0.y, acc.y);
    }
    int c0 = lane * 2, c1 = lane * 2 + 1;
    float h0 = fmaxf(acc.x + b2[c0], 0.f);
    float h1 = fmaxf(acc.y + b2[c1], 0.f);
    float o0 = h0 * Wl[c0 * 2 + 0] + h1 * Wl[c1 * 2 + 0];
    float o1 = h0 * Wl[c0 * 2 + 1] + h1 * Wl[c1 * 2 + 1];
    #pragma unroll
    for (int off = 16; off; off >>= 1) {
        o0 += __shfl_xor_sync(0xffffffffu, o0, off);
        o1 += __shfl_xor_sync(0xffffffffu, o1, off);
    }
    if (lane == 0) {
        out[gw * 2 + 0] = o0 + bl[0];
        out[gw * 2 + 1] = o1 + bl[1];
    }
}

// ---------------- TF32 tensor-core GEMM: macros only, named scalars ----------------
__device__ __forceinline__ unsigned f2tf32(float f) {
    unsigned r;
    asm("cvt.rna.tf32.f32 %0, %1;" : "=r"(r) : "f"(f));
    return r;
}

#define SPLIT1(v, h, l) do { float _v = (v); (h) = f2tf32(_v); (l) = f2tf32(_v - __uint_as_float(h)); } while (0)

#define MMA4(c0, c1, c2, c3, a0, a1, a2, a3, b0, b1)                              \
    asm volatile(                                                                 \
        "mma.sync.aligned.m16n8k8.row.col.f32.tf32.tf32.f32 "                     \
        "{%0,%1,%2,%3},{%4,%5,%6,%7},{%8,%9},{%0,%1,%2,%3};"                      \
        : "+f"(c0), "+f"(c1), "+f"(c2), "+f"(c3)                                  \
        : "r"(a0), "r"(a1), "r"(a2), "r"(a3), "r"(b0), "r"(b1))

// 3-term split product: hi*hi + hi*lo + lo*hi (error ~2^-22)
#define MMA3T(c0, c1, c2, c3, ah0, ah1, ah2, ah3, al0, al1, al2, al3, bh0, bh1, bl0, bl1) \
    do {                                                                          \
        MMA4(c0, c1, c2, c3, ah0, ah1, ah2, ah3, bh0, bh1);                       \
        MMA4(c0, c1, c2, c3, ah0, ah1, ah2, ah3, bl0, bl1);                       \
        MMA4(c0, c1, c2, c3, al0, al1, al2, al3, bh0, bh1);                       \
    } while (0)

// A fragment (row-major m16k8) from AP[r][k] stride ST: rows rb, rb+8; cols k0, k0+4
#define LOADA(AP, ST, rb, k0, h0, h1, h2, h3, l0, l1, l2, l3)                     \
    do {                                                                          \
        SPLIT1((AP)[(rb) * (ST) + (k0)],           h0, l0);                       \
        SPLIT1((AP)[((rb) + 8) * (ST) + (k0)],     h1, l1);                       \
        SPLIT1((AP)[(rb) * (ST) + (k0) + 4],       h2, l2);                       \
        SPLIT1((AP)[((rb) + 8) * (ST) + (k0) + 4], h3, l3);                       \
    } while (0)

// B fragment (col-major n8k8) from BP[n][k] stride ST: col n; rows k0, k0+4
#define LOADB(BP, ST, n, k0, h0, h1, l0, l1)                                      \
    do {                                                                          \
        SPLIT1((BP)[(n) * (ST) + (k0)],     h0, l0);                              \
        SPLIT1((BP)[(n) * (ST) + (k0) + 4], h1, l1);                              \
    } while (0)

// store one frag to global: rows gr, gr+8 at cols cc, cc+1 (NN-guarded)
#define STORE_FRAG(C, NOUT, gr, cc, v0, v1, v2, v3)                               \
    do {                                                                          \
        if ((gr) < NN) {                                                          \
            (C)[(size_t)(gr) * (NOUT) + (cc)]     = (v0);                         \
            (C)[(size_t)(gr) * (NOUT) + (cc) + 1] = (v1);                         \
        }                                                                         \
        if ((gr) + 8 < NN) {                                                      \
            (C)[(size_t)((gr) + 8) * (NOUT) + (cc)]     = (v2);                   \
            (C)[(size_t)((gr) + 8) * (NOUT) + (cc) + 1] = (v3);                   \
        }                                                                         \
    } while (0)

// write one frag to smem h1 tile (stride 132) with bias+relu
#define STORE_H1(H, lr, cc, v0, v1, v2, v3, bias)                                 \
    do {                                                                          \
        float _b0 = (bias)[cc], _b1 = (bias)[(cc) + 1];                           \
        (H)[(lr) * 132 + (cc)]           = fmaxf((v0) + _b0, 0.f);                \
        (H)[(lr) * 132 + (cc) + 1]       = fmaxf((v1) + _b1, 0.f);                \
        (H)[((lr) + 8) * 132 + (cc)]     = fmaxf((v2) + _b0, 0.f);                \
        (H)[((lr) + 8) * 132 + (cc) + 1] = fmaxf((v3) + _b1, 0.f);                \
    } while (0)

// Fused agg + conv1 GEMM + conv2 GEMM (per block of 64 nodes):
//   phase 0: AG[64][132] = agg(x) for nodes rowb..rowb+63  (smem, fp32, MLP=4)
//   phase 1: h1 = relu(AG@W1 + b1) -> H (same smem region, [64][132])
//   phase 2: p2[rowb:rowb+64] = H @ W2 -> global
// 256 threads = 8 warps (2m x 4n). Phase1 warp tile 32x32; phase2 32x16.
// W staged in 16-k chunks, stride 20 (bank = (20*tg + tk) mod 32, conflict-free).
// Static smem: AG/H [64][132] @0 (8448 floats) + WT [128][20] @8448 (2560) = 43KB.
__global__ __launch_bounds__(256) void k_fused(const float* __restrict__ x,
                                               const float* __restrict__ W1,
                                               const float* __restrict__ b1,
                                               const float* __restrict__ W2) {
    __shared__ float SM[11008];

    const int tid  = threadIdx.x;
    const int lane = tid & 31;
    const int wid  = tid >> 5;
    const int rowb = blockIdx.x * 64;
    const int tg   = lane >> 2;
    const int tk   = lane & 3;
    const int row0 = (wid >> 2) * 32;   // 0 or 32

    // ---------------- phase 0: aggregate 64 nodes into AG [64][132], MLP=4 ----------------
    {
        float* AG = SM;
        #pragma unroll 1
        for (int j = 0; j < 8; j++) {
            const int ln = wid * 8 + j;
            const int gw = rowb + ln;
            float4 acc = make_float4(0.f, 0.f, 0.f, 0.f);
            if (gw < NN) {
                int beg = gw ? g_rowptr[gw - 1] : 0;
                int end = g_rowptr[gw];
                int e = beg;
                for (; e + 4 <= end; e += 4) {
                    int2  e0 = g_edge[e],     e1 = g_edge[e + 1];
                    int2  e2 = g_edge[e + 2], e3 = g_edge[e + 3];
                    float4 v0 = ((const float4*)(x + (size_t)e0.x * 128))[lane];
                    float4 v1 = ((const float4*)(x + (size_t)e1.x * 128))[lane];
                    float4 v2 = ((const float4*)(x + (size_t)e2.x * 128))[lane];
                    float4 v3 = ((const float4*)(x + (size_t)e3.x * 128))[lane];
                    float w0 = __int_as_float(e0.y), w1 = __int_as_float(e1.y);
                    float w2 = __int_as_float(e2.y), w3 = __int_as_float(e3.y);
                    acc.x = fmaf(w0, v0.x, acc.x); acc.y = fmaf(w0, v0.y, acc.y);
                    acc.z = fmaf(w0, v0.z, acc.z); acc.w = fmaf(w0, v0.w, acc.w);
                    acc.x = fmaf(w1, v1.x, acc.x); acc.y = fmaf(w1, v1.y, acc.y);
                    acc.z = fmaf(w1, v1.z, acc.z); acc.w = fmaf(w1, v1.w, acc.w);
                    acc.x = fmaf(w2, v2.x, acc.x); acc.y = fmaf(w2, v2.y, acc.y);
                    acc.z = fmaf(w2, v2.z, acc.z); acc.w = fmaf(w2, v2.w, acc.w);
                    acc.x = fmaf(w3, v3.x, acc.x); acc.y = fmaf(w3, v3.y, acc.y);
                    acc.z = fmaf(w3, v3.z, acc.z); acc.w = fmaf(w3, v3.w, acc.w);
                }
                for (; e < end; e++) {
                    int2  e0 = g_edge[e];
                    float w0 = __int_as_float(e0.y);
                    float4 v0 = ((const float4*)(x + (size_t)e0.x * 128))[lane];
                    acc.x = fmaf(w0, v0.x, acc.x); acc.y = fmaf(w0, v0.y, acc.y);
                    acc.z = fmaf(w0, v0.z, acc.z); acc.w = fmaf(w0, v0.w, acc.w);
                }
            }
            float* q = AG + ln * 132 + lane * 4;
            q[0] = acc.x; q[1] = acc.y; q[2] = acc.z; q[3] = acc.w;
        }
    }
    __syncthreads();

    // ---------------- phase 1: h1 = relu(AG@W1 + b1) ----------------
    {
        const float* AG = SM;        // [64][132], read-only this phase
        float* WT1 = SM + 8448;      // [128][20] chunk (16 k-rows)
        const int n0 = (wid & 3) * 32;

        float c00_0 = 0.f, c00_1 = 0.f, c00_2 = 0.f, c00_3 = 0.f;
        float c01_0 = 0.f, c01_1 = 0.f, c01_2 = 0.f, c01_3 = 0.f;
        float c02_0 = 0.f, c02_1 = 0.f, c02_2 = 0.f, c02_3 = 0.f;
        float c03_0 = 0.f, c03_1 = 0.f, c03_2 = 0.f, c03_3 = 0.f;
        float c10_0 = 0.f, c10_1 = 0.f, c10_2 = 0.f, c10_3 = 0.f;
        float c11_0 = 0.f, c11_1 = 0.f, c11_2 = 0.f, c11_3 = 0.f;
        float c12_0 = 0.f, c12_1 = 0.f, c12_2 = 0.f, c12_3 = 0.f;
        float c13_0 = 0.f, c13_1 = 0.f, c13_2 = 0.f, c13_3 = 0.f;

        #pragma unroll 1
        for (int kc = 0; kc < 8; kc++) {      // K chunks of 16
            if (kc) __syncthreads();
            for (int i = tid; i < 16 * 128; i += 256) {
                int k = i >> 7;
                int n = i & 127;
                WT1[n * 20 + k] = W1[(kc * 16 + k) * 128 + n];
            }
            __syncthreads();

            #pragma unroll 1
            for (int inner = 0; inner < 2; inner++) {
                const int k0s = inner * 8 + tk;          // within chunk [0,16)
                const int k0a = kc * 16 + k0s;           // within AG row [0,128)
                unsigned a0h0, a0h1, a0h2, a0h3, a0l0, a0l1, a0l2, a0l3;
                unsigned a1h0, a1h1, a1h2, a1h3, a1l0, a1l1, a1l2, a1l3;
                LOADA(AG, 132, row0 + tg,      k0a, a0h0, a0h1, a0h2, a0h3, a0l0, a0l1, a0l2, a0l3);
                LOADA(AG, 132, row0 + 16 + tg, k0a, a1h0, a1h1, a1h2, a1h3, a1l0, a1l1, a1l2, a1l3);
                unsigned b0h0, b0h1, b0l0, b0l1;
                unsigned b1h0, b1h1, b1l0, b1l1;
                unsigned b2h0, b2h1, b2l0, b2l1;
                unsigned b3h0, b3h1, b3l0, b3l1;
                LOADB(WT1, 20, n0 + tg,      k0s, b0h0, b0h1, b0l0, b0l1);
                LOADB(WT1, 20, n0 + 8 + tg,  k0s, b1h0, b1h1, b1l0, b1l1);
                LOADB(WT1, 20, n0 + 16 + tg, k0s, b2h0, b2h1, b2l0, b2l1);
                LOADB(WT1, 20, n0 + 24 + tg, k0s, b3h0, b3h1, b3l0, b3l1);
                MMA3T(c00_0, c00_1, c00_2, c00_3, a0h0, a0h1, a0h2, a0h3, a0l0, a0l1, a0l2, a0l3, b0h0, b0h1, b0l0, b0l1);
                MMA3T(c01_0, c01_1, c01_2, c01_3, a0h0, a0h1, a0h2, a0h3, a0l0, a0l1, a0l2, a0l3, b1h0, b1h1, b1l0, b1l1);
                MMA3T(c02_0, c02_1, c02_2, c02_3, a0h0, a0h1, a0h2, a0h3, a0l0, a0l1, a0l2, a0l3, b2h0, b2h1, b2l0, b2l1);
                MMA3T(c03_0, c03_1, c03_2, c03_3, a0h0, a0h1, a0h2, a0h3, a0l0, a0l1, a0l2, a0l3, b3h0, b3h1, b3l0, b3l1);
                MMA3T(c10_0, c10_1, c10_2, c10_3, a1h0, a1h1, a1h2, a1h3, a1l0, a1l1, a1l2, a1l3, b0h0, b0h1, b0l0, b0l1);
                MMA3T(c11_0, c11_1, c11_2, c11_3, a1h0, a1h1, a1h2, a1h3, a1l0, a1l1, a1l2, a1l3, b1h0, b1h1, b1l0, b1l1);
                MMA3T(c12_0, c12_1, c12_2, c12_3, a1h0, a1h1, a1h2, a1h3, a1l0, a1l1, a1l2, a1l3, b2h0, b2h1, b2l0, b2l1);
                MMA3T(c13_0, c13_1, c13_2, c13_3, a1h0, a1h1, a1h2, a1h3, a1l0, a1l1, a1l2, a1l3, b3h0, b3h1, b3l0, b3l1);
            }
        }

        // h1 tile -> smem H [64][132] with bias + relu (overwrites AG after sync)
        __syncthreads();
        {
            float* H = SM;
            const int lr0 = row0 + tg;
            const int lr1 = lr0 + 16;
            const int cb  = n0 + 2 * tk;
            STORE_H1(H, lr0, cb,      c00_0, c00_1, c00_2, c00_3, b1);
            STORE_H1(H, lr0, cb + 8,  c01_0, c01_1, c01_2, c01_3, b1);
            STORE_H1(H, lr0, cb + 16, c02_0, c02_1, c02_2, c02_3, b1);
            STORE_H1(H, lr0, cb + 24, c03_0, c03_1, c03_2, c03_3, b1);
            STORE_H1(H, lr1, cb,      c10_0, c10_1, c10_2, c10_3, b1);
            STORE_H1(H, lr1, cb + 8,  c11_0, c11_1, c11_2, c11_3, b1);
            STORE_H1(H, lr1, cb + 16, c12_0, c12_1, c12_2, c12_3, b1);
            STORE_H1(H, lr1, cb + 24, c13_0, c13_1, c13_2, c13_3, b1);
        }
        __syncthreads();
    }

    // ---------------- phase 2: p2 = h1_tile @ W2 ----------------
    {
        const float* H = SM;         // [64][132]
        float* WT2 = SM + 8448;      // [64][20] chunk (16 k-rows)
        const int n0 = (wid & 3) * 16;

        float c00_0 = 0.f, c00_1 = 0.f, c00_2 = 0.f, c00_3 = 0.f;
        float c01_0 = 0.f, c01_1 = 0.f, c01_2 = 0.f, c01_3 = 0.f;
        float c10_0 = 0.f, c10_1 = 0.f, c10_2 = 0.f, c10_3 = 0.f;
        float c11_0 = 0.f, c11_1 = 0.f, c11_2 = 0.f, c11_3 = 0.f;

        #pragma unroll 1
        for (int kc = 0; kc < 8; kc++) {      // K chunks of 16
            if (kc) __syncthreads();
            for (int i = tid; i < 16 * 64; i += 256) {
                int k = i >> 6;
                int n = i & 63;
                WT2[n * 20 + k] = W2[(kc * 16 + k) * 64 + n];
            }
            __syncthreads();

            #pragma unroll 1
            for (int inner = 0; inner < 2; inner++) {
                const int k0s = inner * 8 + tk;          // within chunk
                const int k0a = kc * 16 + k0s;           // within H row
                unsigned a0h0, a0h1, a0h2, a0h3, a0l0, a0l1, a0l2, a0l3;
                unsigned a1h0, a1h1, a1h2, a1h3, a1l0, a1l1, a1l2, a1l3;
                LOADA(H, 132, row0 + tg,      k0a, a0h0, a0h1, a0h2, a0h3, a0l0, a0l1, a0l2, a0l3);
                LOADA(H, 132, row0 + 16 + tg, k0a, a1h0, a1h1, a1h2, a1h3, a1l0, a1l1, a1l2, a1l3);
                unsigned b0h0, b0h1, b0l0, b0l1;
                unsigned b1h0, b1h1, b1l0, b1l1;
                LOADB(WT2, 20, n0 + tg,     k0s, b0h0, b0h1, b0l0, b0l1);
                LOADB(WT2, 20, n0 + 8 + tg, k0s, b1h0, b1h1, b1l0, b1l1);
                MMA3T(c00_0, c00_1, c00_2, c00_3, a0h0, a0h1, a0h2, a0h3, a0l0, a0l1, a0l2, a0l3, b0h0, b0h1, b0l0, b0l1);
                MMA3T(c01_0, c01_1, c01_2, c01_3, a0h0, a0h1, a0h2, a0h3, a0l0, a0l1, a0l2, a0l3, b1h0, b1h1, b1l0, b1l1);
                MMA3T(c10_0, c10_1, c10_2, c10_3, a1h0, a1h1, a1h2, a1h3, a1l0, a1l1, a1l2, a1l3, b0h0, b0h1, b0l0, b0l1);
                MMA3T(c11_0, c11_1, c11_2, c11_3, a1h0, a1h1, a1h2, a1h3, a1l0, a1l1, a1l2, a1l3, b1h0, b1h1, b1l0, b1l1);
            }
        }

        const int gr0 = rowb + row0 + tg;
        const int gr1 = gr0 + 16;
        const int cb  = n0 + 2 * tk;
        STORE_FRAG(g_p2, 64, gr0, cb,     c00_0, c00_1, c00_2, c00_3);
        STORE_FRAG(g_p2, 64, gr0, cb + 8, c01_0, c01_1, c01_2, c01_3);
        STORE_FRAG(g_p2, 64, gr1, cb,     c10_0, c10_1, c10_2, c10_3);
        STORE_FRAG(g_p2, 64, gr1, cb + 8, c11_0, c11_1, c11_2, c11_3);
    }
}

// ---------------- launch ----------------
extern "C" void kernel_launch(void* const* d_in, const int* in_sizes, int n_in,
                              void* d_out, int out_size) {
    const float* x  = (const float*)d_in[0];
    const int*   ei = (const int*)d_in[1];   // [2,E]: src=ei[0:E], dst=ei[E:2E]
    const float* ew = (const float*)d_in[2];
    const float* W1 = (const float*)d_in[3];
    const float* b1 = (const float*)d_in[4];
    const float* W2 = (const float*)d_in[5];
    const float* b2 = (const float*)d_in[6];
    const float* Wl = (const float*)d_in[7];
    const float* bl = (const float*)d_in[8];
    float* out = (float*)d_out;

    const int NB_E = (EE + 255) / 256;
    const int NB_S = (NN + 1023) / 1024;              // 49
    const int NB_W = (NN * 32 + 255) / 256;           // warp-per-node grid
    const int NB_G = (NN + 63) / 64;                  // 782 fused blocks

    // CSR build (g_deg is zero at entry: zero-init at load + re-zeroed by k_scan23)
    k_hist<<<NB_E, 256>>>(ei);
    k_scan1<<<NB_S, 1024>>>();
    k_scan23<<<NB_S, 1024>>>();
    k_scatter<<<NB_E, 256>>>(ei, ew);

    k_fused<<<NB_G, 256>>>(x, W1, b1, W2);
    k_agg64_out<<<NB_W, 256>>>(b2, Wl, bl, out);
}

// round 14
// speedup vs baseline: 1.0535x; 1.0535x over previous
#include <cuda_runtime.h>

// AMLGCN: 2x GCNConv + Linear head.
//   conv(x) = (segment_sum_dst(w_e * x[src]))@W + b   (linearity reorder)
// Pipeline (6 launches):
//   k_hist       degree histogram + per-edge rank capture (g_rank[e] = order within dst)
//   k_scan1      shfl-based per-block exclusive scan -> partial rowptr + block sums
//   k_scan23     per-block carry + finalize rowptr (exclusive, [NN]=EE) + re-zero g_deg
//   k_scatter    ATOMIC-FREE CSR placement: p = rowptr[d] + rank[e]
//   k_fused      AG = agg(x) rows rowb..+63 -> smem (MLP=2); h1 = relu(AG@W1+b1) -> smem;
//                p2 = h1@W2 -> global   (TF32 mma 3-term split)
//   k_agg64_out  out = relu(agg(p2)+b2)@Wl+bl   (gather MLP=2 + fused head)
// MMA hot path is MACRO-ONLY with individually named scalar registers ->
// zero local memory. No inter-block spin anywhere. Static smem only.

#define NN 50000
#define EE 800000

// ---------------- scratch (device globals; no allocations) ----------------
__device__ int   g_deg[NN];         // zero-initialized at load; invariant: zero at entry
__device__ int   g_rowptr[NN + 1];  // exclusive prefix; [NN] = EE
__device__ int   g_rank[EE];        // per-edge rank within its dst (from hist's atomic)
__device__ int   g_bsum[64];
__device__ int2  g_edge[EE];        // .x = src, .y = bitcast(weight)
__device__ float g_p2[(size_t)NN * 64];

// ---------------- CSR build ----------------
// histogram + rank capture: rank = value returned by the degree atomic
__global__ void k_hist(const int* __restrict__ ei) {
    int e = blockIdx.x * blockDim.x + threadIdx.x;
    if (e < EE) g_rank[e] = atomicAdd(&g_deg[ei[EE + e]], 1);
}

// shfl-based block scan (1024 threads): warp inclusive scan -> warp-sum scan -> offset
__global__ void k_scan1() {
    __shared__ int wsum[32];
    const int t    = threadIdx.x;
    const int lane = t & 31;
    const int w    = t >> 5;
    const int i    = blockIdx.x * 1024 + t;
    int v = (i < NN) ? g_deg[i] : 0;
    int s = v;
    #pragma unroll
    for (int off = 1; off < 32; off <<= 1) {
        int n = __shfl_up_sync(0xffffffffu, s, off);
        if (lane >= off) s += n;
    }
    if (lane == 31) wsum[w] = s;
    __syncthreads();
    if (w == 0) {
        int ws = wsum[lane];
        #pragma unroll
        for (int off = 1; off < 32; off <<= 1) {
            int n = __shfl_up_sync(0xffffffffu, ws, off);
            if (lane >= off) ws += n;
        }
        wsum[lane] = ws;
    }
    __syncthreads();
    int add = w ? wsum[w - 1] : 0;
    s += add;
    if (i < NN) g_rowptr[i] = s - v;          // exclusive within block (partial)
    if (t == 1023) g_bsum[blockIdx.x] = s;    // block total
}

// Each block independently computes its carry (2-warp reduce of bsum[0..b)),
// finalizes rowptr, and zeros g_deg (restores invariant).
__global__ void k_scan23() {
    __shared__ int wred[2];
    __shared__ int carry_s;
    const int t = threadIdx.x;
    const int b = blockIdx.x;
    const int i = b * 1024 + t;
    if (t < 64) {
        int c = (t < b) ? g_bsum[t] : 0;
        #pragma unroll
        for (int off = 16; off; off >>= 1) c += __shfl_down_sync(0xffffffffu, c, off);
        if ((t & 31) == 0) wred[t >> 5] = c;
    }
    __syncthreads();
    if (t == 0) carry_s = wred[0] + wred[1];
    __syncthreads();
    if (i < NN) {
        g_rowptr[i] += carry_s;   // global exclusive prefix
        g_deg[i] = 0;             // restore invariant for next kernel_launch call
    }
    if (b == 0 && t == 0) g_rowptr[NN] = EE;
}

// ATOMIC-FREE scatter: position = rowptr[d] + rank[e]
__global__ void k_scatter(const int* __restrict__ ei, const float* __restrict__ w) {
    int e = blockIdx.x * blockDim.x + threadIdx.x;
    if (e < EE) {
        int d = ei[EE + e];
        int p = g_rowptr[d] + g_rank[e];
        g_edge[p] = make_int2(ei[e], __float_as_int(w[e]));
    }
}

// agg over 64 features (MLP=2) + fused: relu(.+b2) @ Wl + bl  ->  out[N,2]
__global__ void k_agg64_out(const float* __restrict__ b2,
                            const float* __restrict__ Wl,
                            const float* __restrict__ bl,
                            float* __restrict__ out) {
    int gw   = (blockIdx.x * blockDim.x + threadIdx.x) >> 5;
    int lane = threadIdx.x & 31;
    if (gw >= NN) return;
    int beg = g_rowptr[gw];
    int end = g_rowptr[gw + 1];
    float2 acc = make_float2(0.f, 0.f);
    int e = beg;
    for (; e + 2 <= end; e += 2) {
        int2  e0 = g_edge[e], e1 = g_edge[e + 1];
        float w0 = __int_as_float(e0.y), w1 = __int_as_float(e1.y);
        float2 v0 = ((const float2*)(g_p2 + (size_t)e0.x * 64))[lane];
        float2 v1 = ((const float2*)(g_p2 + (size_t)e1.x * 64))[lane];
        acc.x = fmaf(w0, v0.x, acc.x); acc.y = fmaf(w0, v0.y, acc.y);
        acc.x = fmaf(w1, v1.x, acc.x); acc.y = fmaf(w1, v1.y, acc.y);
    }
    if (e < end) {
        int2  e0 = g_edge[e];
        float w0 = __int_as_float(e0.y);
        float2 v0 = ((const float2*)(g_p2 + (size_t)e0.x * 64))[lane];
        acc.x = fmaf(w0, v0.x, acc.x); acc.y = fmaf(w0, v0.y, acc.y);
    }
    int c0 = lane * 2, c1 = lane * 2 + 1;
    float h0 = fmaxf(acc.x + b2[c0], 0.f);
    float h1 = fmaxf(acc.y + b2[c1], 0.f);
    float o0 = h0 * Wl[c0 * 2 + 0] + h1 * Wl[c1 * 2 + 0];
    float o1 = h0 * Wl[c0 * 2 + 1] + h1 * Wl[c1 * 2 + 1];
    #pragma unroll
    for (int off = 16; off; off >>= 1) {
        o0 += __shfl_xor_sync(0xffffffffu, o0, off);
        o1 += __shfl_xor_sync(0xffffffffu, o1, off);
    }
    if (lane == 0) {
        out[gw * 2 + 0] = o0 + bl[0];
        out[gw * 2 + 1] = o1 + bl[1];
    }
}

// ---------------- TF32 tensor-core GEMM: macros only, named scalars ----------------
__device__ __forceinline__ unsigned f2tf32(float f) {
    unsigned r;
    asm("cvt.rna.tf32.f32 %0, %1;" : "=r"(r) : "f"(f));
    return r;
}

#define SPLIT1(v, h, l) do { float _v = (v); (h) = f2tf32(_v); (l) = f2tf32(_v - __uint_as_float(h)); } while (0)

#define MMA4(c0, c1, c2, c3, a0, a1, a2, a3, b0, b1)                              \
    asm volatile(                                                                 \
        "mma.sync.aligned.m16n8k8.row.col.f32.tf32.tf32.f32 "                     \
        "{%0,%1,%2,%3},{%4,%5,%6,%7},{%8,%9},{%0,%1,%2,%3};"                      \
        : "+f"(c0), "+f"(c1), "+f"(c2), "+f"(c3)                                  \
        : "r"(a0), "r"(a1), "r"(a2), "r"(a3), "r"(b0), "r"(b1))

// 3-term split product: hi*hi + hi*lo + lo*hi (error ~2^-22)
#define MMA3T(c0, c1, c2, c3, ah0, ah1, ah2, ah3, al0, al1, al2, al3, bh0, bh1, bl0, bl1) \
    do {                                                                          \
        MMA4(c0, c1, c2, c3, ah0, ah1, ah2, ah3, bh0, bh1);                       \
        MMA4(c0, c1, c2, c3, ah0, ah1, ah2, ah3, bl0, bl1);                       \
        MMA4(c0, c1, c2, c3, al0, al1, al2, al3, bh0, bh1);                       \
    } while (0)

// A fragment (row-major m16k8) from AP[r][k] stride ST: rows rb, rb+8; cols k0, k0+4
#define LOADA(AP, ST, rb, k0, h0, h1, h2, h3, l0, l1, l2, l3)                     \
    do {                                                                          \
        SPLIT1((AP)[(rb) * (ST) + (k0)],           h0, l0);                       \
        SPLIT1((AP)[((rb) + 8) * (ST) + (k0)],     h1, l1);                       \
        SPLIT1((AP)[(rb) * (ST) + (k0) + 4],       h2, l2);                       \
        SPLIT1((AP)[((rb) + 8) * (ST) + (k0) + 4], h3, l3);                       \
    } while (0)

// B fragment (col-major n8k8) from BP[n][k] stride ST: col n; rows k0, k0+4
#define LOADB(BP, ST, n, k0, h0, h1, l0, l1)                                      \
    do {                                                                          \
        SPLIT1((BP)[(n) * (ST) + (k0)],     h0, l0);                              \
        SPLIT1((BP)[(n) * (ST) + (k0) + 4], h1, l1);                              \
    } while (0)

// store one frag to global: rows gr, gr+8 at cols cc, cc+1 (NN-guarded)
#define STORE_FRAG(C, NOUT, gr, cc, v0, v1, v2, v3)                               \
    do {                                                                          \
        if ((gr) < NN) {                                                          \
            (C)[(size_t)(gr) * (NOUT) + (cc)]     = (v0);                         \
            (C)[(size_t)(gr) * (NOUT) + (cc) + 1] = (v1);                         \
        }                                                                         \
        if ((gr) + 8 < NN) {                                                      \
            (C)[(size_t)((gr) + 8) * (NOUT) + (cc)]     = (v2);                   \
            (C)[(size_t)((gr) + 8) * (NOUT) + (cc) + 1] = (v3);                   \
        }                                                                         \
    } while (0)

// write one frag to smem h1 tile (stride 132) with bias+relu
#define STORE_H1(H, lr, cc, v0, v1, v2, v3, bias)                                 \
    do {                                                                          \
        float _b0 = (bias)[cc], _b1 = (bias)[(cc) + 1];                           \
        (H)[(lr) * 132 + (cc)]           = fmaxf((v0) + _b0, 0.f);                \
        (H)[(lr) * 132 + (cc) + 1]       = fmaxf((v1) + _b1, 0.f);                \
        (H)[((lr) + 8) * 132 + (cc)]     = fmaxf((v2) + _b0, 0.f);                \
        (H)[((lr) + 8) * 132 + (cc) + 1] = fmaxf((v3) + _b1, 0.f);                \
    } while (0)

// Fused agg + conv1 GEMM + conv2 GEMM (per block of 64 nodes):
//   phase 0: AG[64][132] = agg(x) for nodes rowb..rowb+63  (smem, fp32, MLP=2)
//   phase 1: h1 = relu(AG@W1 + b1) -> H (same smem region, [64][132])
//   phase 2: p2[rowb:rowb+64] = H @ W2 -> global
// 256 threads = 8 warps (2m x 4n). Phase1 warp tile 32x32; phase2 32x16.
// W staged in 16-k chunks, stride 20 (bank = (20*tg + tk) mod 32, conflict-free).
// Static smem: AG/H [64][132] @0 (8448 floats) + WT [128][20] @8448 (2560) = 43KB.
__global__ __launch_bounds__(256) void k_fused(const float* __restrict__ x,
                                               const float* __restrict__ W1,
                                               const float* __restrict__ b1,
                                               const float* __restrict__ W2) {
    __shared__ float SM[11008];

    const int tid  = threadIdx.x;
    const int lane = tid & 31;
    const int wid  = tid >> 5;
    const int rowb = blockIdx.x * 64;
    const int tg   = lane >> 2;
    const int tk   = lane & 3;
    const int row0 = (wid >> 2) * 32;   // 0 or 32

    // ---------------- phase 0: aggregate 64 nodes into AG [64][132], MLP=2 ----------------
    {
        float* AG = SM;
        #pragma unroll 1
        for (int j = 0; j < 8; j++) {
            const int ln = wid * 8 + j;
            const int gw = rowb + ln;
            float4 acc = make_float4(0.f, 0.f, 0.f, 0.f);
            if (gw < NN) {
                int beg = g_rowptr[gw];
                int end = g_rowptr[gw + 1];
                int e = beg;
                for (; e + 2 <= end; e += 2) {
                    int2  e0 = g_edge[e], e1 = g_edge[e + 1];
                    float w0 = __int_as_float(e0.y), w1 = __int_as_float(e1.y);
                    float4 v0 = ((const float4*)(x + (size_t)e0.x * 128))[lane];
                    float4 v1 = ((const float4*)(x + (size_t)e1.x * 128))[lane];
                    acc.x = fmaf(w0, v0.x, acc.x); acc.y = fmaf(w0, v0.y, acc.y);
                    acc.z = fmaf(w0, v0.z, acc.z); acc.w = fmaf(w0, v0.w, acc.w);
                    acc.x = fmaf(w1, v1.x, acc.x); acc.y = fmaf(w1, v1.y, acc.y);
                    acc.z = fmaf(w1, v1.z, acc.z); acc.w = fmaf(w1, v1.w, acc.w);
                }
                if (e < end) {
                    int2  e0 = g_edge[e];
                    float w0 = __int_as_float(e0.y);
                    float4 v0 = ((const float4*)(x + (size_t)e0.x * 128))[lane];
                    acc.x = fmaf(w0, v0.x, acc.x); acc.y = fmaf(w0, v0.y, acc.y);
                    acc.z = fmaf(w0, v0.z, acc.z); acc.w = fmaf(w0, v0.w, acc.w);
                }
            }
            float* q = AG + ln * 132 + lane * 4;
            q[0] = acc.x; q[1] = acc.y; q[2] = acc.z; q[3] = acc.w;
        }
    }
    __syncthreads();

    // ---------------- phase 1: h1 = relu(AG@W1 + b1) ----------------
    {
        const float* AG = SM;        // [64][132], read-only this phase
        float* WT1 = SM + 8448;      // [128][20] chunk (16 k-rows)
        const int n0 = (wid & 3) * 32;

        float c00_0 = 0.f, c00_1 = 0.f, c00_2 = 0.f, c00_3 = 0.f;
        float c01_0 = 0.f, c01_1 = 0.f, c01_2 = 0.f, c01_3 = 0.f;
        float c02_0 = 0.f, c02_1 = 0.f, c02_2 = 0.f, c02_3 = 0.f;
        float c03_0 = 0.f, c03_1 = 0.f, c03_2 = 0.f, c03_3 = 0.f;
        float c10_0 = 0.f, c10_1 = 0.f, c10_2 = 0.f, c10_3 = 0.f;
        float c11_0 = 0.f, c11_1 = 0.f, c11_2 = 0.f, c11_3 = 0.f;
        float c12_0 = 0.f, c12_1 = 0.f, c12_2 = 0.f, c12_3 = 0.f;
        float c13_0 = 0.f, c13_1 = 0.f, c13_2 = 0.f, c13_3 = 0.f;

        #pragma unroll 1
        for (int kc = 0; kc < 8; kc++) {      // K chunks of 16
            if (kc) __syncthreads();
            for (int i = tid; i < 16 * 128; i += 256) {
                int k = i >> 7;
                int n = i & 127;
                WT1[n * 20 + k] = W1[(kc * 16 + k) * 128 + n];
            }
            __syncthreads();

            #pragma unroll 1
            for (int inner = 0; inner < 2; inner++) {
                const int k0s = inner * 8 + tk;          // within chunk [0,16)
                const int k0a = kc * 16 + k0s;           // within AG row [0,128)
                unsigned a0h0, a0h1, a0h2, a0h3, a0l0, a0l1, a0l2, a0l3;
                unsigned a1h0, a1h1, a1h2, a1h3, a1l0, a1l1, a1l2, a1l3;
                LOADA(AG, 132, row0 + tg,      k0a, a0h0, a0h1, a0h2, a0h3, a0l0, a0l1, a0l2, a0l3);
                LOADA(AG, 132, row0 + 16 + tg, k0a, a1h0, a1h1, a1h2, a1h3, a1l0, a1l1, a1l2, a1l3);
                unsigned b0h0, b0h1, b0l0, b0l1;
                unsigned b1h0, b1h1, b1l0, b1l1;
                unsigned b2h0, b2h1, b2l0, b2l1;
                unsigned b3h0, b3h1, b3l0, b3l1;
                LOADB(WT1, 20, n0 + tg,      k0s, b0h0, b0h1, b0l0, b0l1);
                LOADB(WT1, 20, n0 + 8 + tg,  k0s, b1h0, b1h1, b1l0, b1l1);
                LOADB(WT1, 20, n0 + 16 + tg, k0s, b2h0, b2h1, b2l0, b2l1);
                LOADB(WT1, 20, n0 + 24 + tg, k0s, b3h0, b3h1, b3l0, b3l1);
                MMA3T(c00_0, c00_1, c00_2, c00_3, a0h0, a0h1, a0h2, a0h3, a0l0, a0l1, a0l2, a0l3, b0h0, b0h1, b0l0, b0l1);
                MMA3T(c01_0, c01_1, c01_2, c01_3, a0h0, a0h1, a0h2, a0h3, a0l0, a0l1, a0l2, a0l3, b1h0, b1h1, b1l0, b1l1);
                MMA3T(c02_0, c02_1, c02_2, c02_3, a0h0, a0h1, a0h2, a0h3, a0l0, a0l1, a0l2, a0l3, b2h0, b2h1, b2l0, b2l1);
                MMA3T(c03_0, c03_1, c03_2, c03_3, a0h0, a0h1, a0h2, a0h3, a0l0, a0l1, a0l2, a0l3, b3h0, b3h1, b3l0, b3l1);
                MMA3T(c10_0, c10_1, c10_2, c10_3, a1h0, a1h1, a1h2, a1h3, a1l0, a1l1, a1l2, a1l3, b0h0, b0h1, b0l0, b0l1);
                MMA3T(c11_0, c11_1, c11_2, c11_3, a1h0, a1h1, a1h2, a1h3, a1l0, a1l1, a1l2, a1l3, b1h0, b1h1, b1l0, b1l1);
                MMA3T(c12_0, c12_1, c12_2, c12_3, a1h0, a1h1, a1h2, a1h3, a1l0, a1l1, a1l2, a1l3, b2h0, b2h1, b2l0, b2l1);
                MMA3T(c13_0, c13_1, c13_2, c13_3, a1h0, a1h1, a1h2, a1h3, a1l0, a1l1, a1l2, a1l3, b3h0, b3h1, b3l0, b3l1);
            }
        }

        // h1 tile -> smem H [64][132] with bias + relu (overwrites AG after sync)
        __syncthreads();
        {
            float* H = SM;
            const int lr0 = row0 + tg;
            const int lr1 = lr0 + 16;
            const int cb  = n0 + 2 * tk;
            STORE_H1(H, lr0, cb,      c00_0, c00_1, c00_2, c00_3, b1);
            STORE_H1(H, lr0, cb + 8,  c01_0, c01_1, c01_2, c01_3, b1);
            STORE_H1(H, lr0, cb + 16, c02_0, c02_1, c02_2, c02_3, b1);
            STORE_H1(H, lr0, cb + 24, c03_0, c03_1, c03_2, c03_3, b1);
            STORE_H1(H, lr1, cb,      c10_0, c10_1, c10_2, c10_3, b1);
            STORE_H1(H, lr1, cb + 8,  c11_0, c11_1, c11_2, c11_3, b1);
            STORE_H1(H, lr1, cb + 16, c12_0, c12_1, c12_2, c12_3, b1);
            STORE_H1(H, lr1, cb + 24, c13_0, c13_1, c13_2, c13_3, b1);
        }
        __syncthreads();
    }

    // ---------------- phase 2: p2 = h1_tile @ W2 ----------------
    {
        const float* H = SM;         // [64][132]
        float* WT2 = SM + 8448;      // [64][20] chunk (16 k-rows)
        const int n0 = (wid & 3) * 16;

        float c00_0 = 0.f, c00_1 = 0.f, c00_2 = 0.f, c00_3 = 0.f;
        float c01_0 = 0.f, c01_1 = 0.f, c01_2 = 0.f, c01_3 = 0.f;
        float c10_0 = 0.f, c10_1 = 0.f, c10_2 = 0.f, c10_3 = 0.f;
        float c11_0 = 0.f, c11_1 = 0.f, c11_2 = 0.f, c11_3 = 0.f;

        #pragma unroll 1
        for (int kc = 0; kc < 8; kc++) {      // K chunks of 16
            if (kc) __syncthreads();
            for (int i = tid; i < 16 * 64; i += 256) {
                int k = i >> 6;
                int n = i & 63;
                WT2[n * 20 + k] = W2[(kc * 16 + k) * 64 + n];
            }
            __syncthreads();

            #pragma unroll 1
            for (int inner = 0; inner < 2; inner++) {
                const int k0s = inner * 8 + tk;          // within chunk
                const int k0a = kc * 16 + k0s;           // within H row
                unsigned a0h0, a0h1, a0h2, a0h3, a0l0, a0l1, a0l2, a0l3;
                unsigned a1h0, a1h1, a1h2, a1h3, a1l0, a1l1, a1l2, a1l3;
                LOADA(H, 132, row0 + tg,      k0a, a0h0, a0h1, a0h2, a0h3, a0l0, a0l1, a0l2, a0l3);
                LOADA(H, 132, row0 + 16 + tg, k0a, a1h0, a1h1, a1h2, a1h3, a1l0, a1l1, a1l2, a1l3);
                unsigned b0h0, b0h1, b0l0, b0l1;
                unsigned b1h0, b1h1, b1l0, b1l1;
                LOADB(WT2, 20, n0 + tg,     k0s, b0h0, b0h1, b0l0, b0l1);
                LOADB(WT2, 20, n0 + 8 + tg, k0s, b1h0, b1h1, b1l0, b1l1);
                MMA3T(c00_0, c00_1, c00_2, c00_3, a0h0, a0h1, a0h2, a0h3, a0l0, a0l1, a0l2, a0l3, b0h0, b0h1, b0l0, b0l1);
                MMA3T(c01_0, c01_1, c01_2, c01_3, a0h0, a0h1, a0h2, a0h3, a0l0, a0l1, a0l2, a0l3, b1h0, b1h1, b1l0, b1l1);
                MMA3T(c10_0, c10_1, c10_2, c10_3, a1h0, a1h1, a1h2, a1h3, a1l0, a1l1, a1l2, a1l3, b0h0, b0h1, b0l0, b0l1);
                MMA3T(c11_0, c11_1, c11_2, c11_3, a1h0, a1h1, a1h2, a1h3, a1l0, a1l1, a1l2, a1l3, b1h0, b1h1, b1l0, b1l1);
            }
        }

        const int gr0 = rowb + row0 + tg;
        const int gr1 = gr0 + 16;
        const int cb  = n0 + 2 * tk;
        STORE_FRAG(g_p2, 64, gr0, cb,     c00_0, c00_1, c00_2, c00_3);
        STORE_FRAG(g_p2, 64, gr0, cb + 8, c01_0, c01_1, c01_2, c01_3);
        STORE_FRAG(g_p2, 64, gr1, cb,     c10_0, c10_1, c10_2, c10_3);
        STORE_FRAG(g_p2, 64, gr1, cb + 8, c11_0, c11_1, c11_2, c11_3);
    }
}

// ---------------- launch ----------------
extern "C" void kernel_launch(void* const* d_in, const int* in_sizes, int n_in,
                              void* d_out, int out_size) {
    const float* x  = (const float*)d_in[0];
    const int*   ei = (const int*)d_in[1];   // [2,E]: src=ei[0:E], dst=ei[E:2E]
    const float* ew = (const float*)d_in[2];
    const float* W1 = (const float*)d_in[3];
    const float* b1 = (const float*)d_in[4];
    const float* W2 = (const float*)d_in[5];
    const float* b2 = (const float*)d_in[6];
    const float* Wl = (const float*)d_in[7];
    const float* bl = (const float*)d_in[8];
    float* out = (float*)d_out;

    const int NB_E = (EE + 255) / 256;
    const int NB_S = (NN + 1023) / 1024;              // 49
    const int NB_W = (NN * 32 + 255) / 256;           // warp-per-node grid
    const int NB_G = (NN + 63) / 64;                  // 782 fused blocks

    // CSR build (g_deg is zero at entry: zero-init at load + re-zeroed by k_scan23)
    k_hist<<<NB_E, 256>>>(ei);
    k_scan1<<<NB_S, 1024>>>();
    k_scan23<<<NB_S, 1024>>>();
    k_scatter<<<NB_E, 256>>>(ei, ew);

    k_fused<<<NB_G, 256>>>(x, W1, b1, W2);
    k_agg64_out<<<NB_W, 256>>>(b2, Wl, bl, out);
}